// round 13
// baseline (speedup 1.0000x reference)
#include <cuda_runtime.h>
#include <cuda_fp16.h>
#include <cstdint>

// HypercomplexLinear via Winograd-optimal (5-multiplication) length-4 cyclic
// convolution + fp16 mma.sync m16n8k16 (round-8/12 engine, at the sm_103a
// legacy-tensor MAC ceiling; only FLOPs reduced this round).
//   a0 = X0@W0'^T, a2 = X2@W2'^T           (K=192 each)
//   m1 = Xr@Wr'^T, m2 = Xs@Ws'^T, m3 = (Xr+Xs)@(Wr'+Ws')^T   (K=192 each)
//   P = m1-m2, Q = m3-m1-m2
//   out_0=a0+a2+P, out_1=a0-a2+Q, out_2=a0+a2-P, out_3=a0-a2-Q  (+bias)
// G = [a0|a2|m1|m2|m3] fp16 intermediate (row width 3840), combine -> fp32.

#define M_DIM 6272
#define KXO   768     // original x row width
#define KXT   960     // g_Xt row width: [X0|X2|Xr|Xs|Xr+Xs]
#define NGW   3840    // g_G row width

__device__ __half g_Xt[M_DIM * KXT];
// g_Bp: comp c (0..4) * 147456 + tile(0..5)*24576 + chunk(0..2)*8192 + n*64
__device__ __half g_Bp[737280];
__device__ __half g_G[M_DIM * NGW];

// ---------------------------------------------------------------------------
// Prep 1: X transforms -> fp16. One thread per 4 c per row (301k threads).
// ---------------------------------------------------------------------------
__global__ void prep_xt_kernel(const float* __restrict__ x) {
    int idx = blockIdx.x * blockDim.x + threadIdx.x;   // 6272*48
    int b   = idx / 48;
    int c4  = (idx - b * 48) * 4;
    const float* xb = x + (size_t)b * KXO;
    float4 v0 = *reinterpret_cast<const float4*>(xb + c4);
    float4 v1 = *reinterpret_cast<const float4*>(xb + 192 + c4);
    float4 v2 = *reinterpret_cast<const float4*>(xb + 384 + c4);
    float4 v3 = *reinterpret_cast<const float4*>(xb + 576 + c4);
    __half* yb = g_Xt + (size_t)b * KXT + c4;
#pragma unroll
    for (int cmp = 0; cmp < 5; cmp++) {
        float c0, c1, c2, c3;
        if (cmp == 0) { c0 = v0.x+v1.x+v2.x+v3.x; c1 = v0.y+v1.y+v2.y+v3.y;
                        c2 = v0.z+v1.z+v2.z+v3.z; c3 = v0.w+v1.w+v2.w+v3.w; }
        else if (cmp == 1) { c0 = v0.x-v1.x+v2.x-v3.x; c1 = v0.y-v1.y+v2.y-v3.y;
                             c2 = v0.z-v1.z+v2.z-v3.z; c3 = v0.w-v1.w+v2.w-v3.w; }
        else if (cmp == 2) { c0 = v0.x-v2.x; c1 = v0.y-v2.y;
                             c2 = v0.z-v2.z; c3 = v0.w-v2.w; }
        else if (cmp == 3) { c0 = v1.x-v3.x; c1 = v1.y-v3.y;
                             c2 = v1.z-v3.z; c3 = v1.w-v3.w; }
        else { c0 = v0.x-v2.x+v1.x-v3.x; c1 = v0.y-v2.y+v1.y-v3.y;
               c2 = v0.z-v2.z+v1.z-v3.z; c3 = v0.w-v2.w+v1.w-v3.w; }
        __half2 h0 = __floats2half2_rn(c0, c1);
        __half2 h1 = __floats2half2_rn(c2, c3);
        uint2 packed;
        packed.x = *reinterpret_cast<uint32_t*>(&h0);
        packed.y = *reinterpret_cast<uint32_t*>(&h1);
        *reinterpret_cast<uint2*>(yb + cmp * 192) = packed;
    }
}

// ---------------------------------------------------------------------------
// Prep 2: pack 5 weight components -> fp16, [n][64k] rows per chunk.
// ---------------------------------------------------------------------------
__global__ void prep_bp_kernel(const float* __restrict__ w) {
    int idx = blockIdx.x * blockDim.x + threadIdx.x;   // 11520
    int c    = idx / 2304;                 // component 0..4
    int r    = idx - c * 2304;
    int tile = r / 384;                    // 0..5
    int rem  = r - tile * 384;
    int cc   = rem >> 7;                   // chunk 0..2
    int n    = rem & 127;
    int o    = tile * 128 + n;
    const float* b0 = w + o * 192 + cc * 64;

    __half h[64];
#pragma unroll 8
    for (int kk = 0; kk < 64; kk++) {
        float w0 = b0[kk], w1 = b0[147456 + kk];
        float w2 = b0[294912 + kk], w3 = b0[442368 + kk];
        float val;
        if (c == 0)      val = 0.25f * (w0 + w1 + w2 + w3);
        else if (c == 1) val = 0.25f * (w0 - w1 + w2 - w3);
        else if (c == 2) val = 0.5f * (w0 - w2);
        else if (c == 3) val = 0.5f * (w1 - w3);
        else             val = 0.5f * (w0 - w2 + w1 - w3);
        h[kk] = __float2half_rn(val);
    }
    __half* dst = g_Bp + c * 147456 + tile * 24576 + cc * 8192 + n * 64;
#pragma unroll
    for (int q = 0; q < 8; q++)
        reinterpret_cast<uint4*>(dst)[q] = reinterpret_cast<const uint4*>(h)[q];
}

// ---------------------------------------------------------------------------
// fp16 GEMM with ldmatrix. CTA 128x128, K=192 (3 chunks of 64), 3-stage
// cp.async, 2 CTAs/SM. Grid (30, 49) — 5 components x 6 n-tiles, uniform.
// ---------------------------------------------------------------------------
#define STAGES 3
#define STG_B 32768
#define SMEM_BYTES (STAGES * STG_B)

__device__ __forceinline__ void mma_f16(float* c, uint32_t a0, uint32_t a1,
                                        uint32_t a2, uint32_t a3,
                                        uint32_t b0, uint32_t b1) {
    asm volatile(
        "mma.sync.aligned.m16n8k16.row.col.f32.f16.f16.f32 "
        "{%0,%1,%2,%3}, {%4,%5,%6,%7}, {%8,%9}, {%0,%1,%2,%3};"
        : "+f"(c[0]), "+f"(c[1]), "+f"(c[2]), "+f"(c[3])
        : "r"(a0), "r"(a1), "r"(a2), "r"(a3), "r"(b0), "r"(b1));
}
#define LDSM_X4(r0, r1, r2, r3, a) \
    asm volatile("ldmatrix.sync.aligned.m8n8.x4.shared.b16 {%0,%1,%2,%3}, [%4];" \
                 : "=r"(r0), "=r"(r1), "=r"(r2), "=r"(r3) : "r"(a))

__global__ __launch_bounds__(256, 2)
void gemm_f16_kernel() {
    extern __shared__ char smem[];
    const int nt  = blockIdx.x;          // 0..29
    const int bm  = blockIdx.y * 128;
    const int bn  = nt * 128;            // column in G (width 3840)

    const int comp = nt / 6;
    const int tt   = nt - comp * 6;
    const int aoff = comp * 192;
    const __half* Bg = g_Bp + comp * 147456 + tt * 24576;
    const int KT = 3;

    const int tid  = threadIdx.x;
    const int warp = tid >> 5;
    const int lane = tid & 31;
    const int g    = lane >> 2;
    const int tig  = lane & 3;
    const int wm   = (warp & 1) * 64;
    const int wn   = (warp >> 1) * 32;

    float acc[4][4][4];
#pragma unroll
    for (int mi = 0; mi < 4; mi++)
#pragma unroll
        for (int ni = 0; ni < 4; ni++)
#pragma unroll
            for (int r = 0; r < 4; r++) acc[mi][ni][r] = 0.0f;

    // cp.async loader: 2 threads per row, 4 x 16B chunks each
    const int lrow = tid >> 1;
    const int cseg = (tid & 1) * 4;
    const int ssw  = lrow & 7;
    const char* gA = reinterpret_cast<const char*>(
        g_Xt + (size_t)(bm + lrow) * KXT + aoff);
    const char* gB = reinterpret_cast<const char*>(Bg + lrow * 64);
    uint32_t sbase;
    asm("{ .reg .u64 t; cvta.to.shared.u64 t, %1; cvt.u32.u64 %0, t; }"
        : "=r"(sbase) : "l"(smem));

    auto load_stage = [&](int kt, int s) {
        uint32_t ab = sbase + (uint32_t)(s * STG_B);
        uint32_t bb = ab + 16384u;
#pragma unroll
        for (int f = 0; f < 4; f++) {
            int c = cseg + f;
            uint32_t wd = (uint32_t)(lrow * 128 + ((c ^ ssw) << 4));
            asm volatile("cp.async.cg.shared.global [%0], [%1], 16;"
                         :: "r"(ab + wd), "l"(gA + kt * 128 + c * 16));
            asm volatile("cp.async.cg.shared.global [%0], [%1], 16;"
                         :: "r"(bb + wd), "l"(gB + kt * 16384 + c * 16));
        }
    };

    // ldmatrix per-lane row mapping
    const int rowA = (lane & 7) + ((lane >> 3) & 1) * 8;
    const int chA  = lane >> 4;
    const int rowB = (lane & 7) + ((lane >> 4) & 1) * 8;
    const int chB  = (lane >> 3) & 1;
    int rA[4], rB[2];
#pragma unroll
    for (int mi = 0; mi < 4; mi++) rA[mi] = wm + mi * 16 + rowA;
#pragma unroll
    for (int n2 = 0; n2 < 2; n2++) rB[n2] = wn + n2 * 16 + rowB;

    auto compute = [&](int s) {
        uint32_t As = sbase + (uint32_t)(s * STG_B);
        uint32_t Bs = As + 16384u;
#pragma unroll
        for (int kg = 0; kg < 4; kg++) {
            uint32_t af[4][4], bf[2][4];
#pragma unroll
            for (int mi = 0; mi < 4; mi++) {
                uint32_t ad = As + (uint32_t)(rA[mi] * 128
                            + (((2 * kg + chA) ^ (rA[mi] & 7)) << 4));
                LDSM_X4(af[mi][0], af[mi][1], af[mi][2], af[mi][3], ad);
            }
#pragma unroll
            for (int n2 = 0; n2 < 2; n2++) {
                uint32_t bd = Bs + (uint32_t)(rB[n2] * 128
                            + (((2 * kg + chB) ^ (rB[n2] & 7)) << 4));
                LDSM_X4(bf[n2][0], bf[n2][1], bf[n2][2], bf[n2][3], bd);
            }
#pragma unroll
            for (int ni = 0; ni < 4; ni++) {
                uint32_t b0 = bf[ni >> 1][(ni & 1) * 2];
                uint32_t b1 = bf[ni >> 1][(ni & 1) * 2 + 1];
#pragma unroll
                for (int mi = 0; mi < 4; mi++)
                    mma_f16(acc[mi][ni], af[mi][0], af[mi][1], af[mi][2], af[mi][3],
                            b0, b1);
            }
        }
    };

    int fetch = 0;
#pragma unroll
    for (int s = 0; s < STAGES - 1; s++) {
        if (fetch < KT) load_stage(fetch, s);
        asm volatile("cp.async.commit_group;");
        fetch++;
    }
    asm volatile("cp.async.wait_group %0;" :: "n"(STAGES - 2));
    __syncthreads();

    for (int kt = 0; kt < KT; kt++) {
        if (fetch < KT) load_stage(fetch, fetch % STAGES);
        asm volatile("cp.async.commit_group;");
        fetch++;
        compute(kt % STAGES);
        asm volatile("cp.async.wait_group %0;" :: "n"(STAGES - 2));
        __syncthreads();
    }

    // Epilogue: acc -> fp16 smem tile (row stride 136) -> coalesced stores
    __half* sg = reinterpret_cast<__half*>(smem);
#pragma unroll
    for (int mi = 0; mi < 4; mi++) {
        int row0 = wm + mi * 16 + g;
#pragma unroll
        for (int ni = 0; ni < 4; ni++) {
            int col = wn + ni * 8 + 2 * tig;
            *reinterpret_cast<__half2*>(sg + row0 * 136 + col) =
                __floats2half2_rn(acc[mi][ni][0], acc[mi][ni][1]);
            *reinterpret_cast<__half2*>(sg + (row0 + 8) * 136 + col) =
                __floats2half2_rn(acc[mi][ni][2], acc[mi][ni][3]);
        }
    }
    __syncthreads();
#pragma unroll
    for (int i = 0; i < 8; i++) {
        int linear = tid + 256 * i;
        int row = linear >> 4;
        int q   = linear & 15;
        uint4 v = *reinterpret_cast<const uint4*>(sg + row * 136 + q * 8);
        *reinterpret_cast<uint4*>(g_G + (size_t)(bm + row) * NGW + bn + q * 8) = v;
    }
}

// ---------------------------------------------------------------------------
// Combine: fp16 G (5 comps) -> fp32 out with bias. One thread per (b, 2 o).
// ---------------------------------------------------------------------------
__global__ void combine_kernel(const float* __restrict__ bias,
                               float* __restrict__ out) {
    int idx = blockIdx.x * blockDim.x + threadIdx.x;   // 6272*384
    int b  = idx / 384;
    int o2 = (idx - b * 384) * 2;
    const __half* Gb = g_G + (size_t)b * NGW;
    __half2 ha0 = *reinterpret_cast<const __half2*>(Gb + o2);
    __half2 ha2 = *reinterpret_cast<const __half2*>(Gb + 768 + o2);
    __half2 hm1 = *reinterpret_cast<const __half2*>(Gb + 1536 + o2);
    __half2 hm2 = *reinterpret_cast<const __half2*>(Gb + 2304 + o2);
    __half2 hm3 = *reinterpret_cast<const __half2*>(Gb + 3072 + o2);

    float2 a0 = __half22float2(ha0);
    float2 a2 = __half22float2(ha2);
    float2 m1 = __half22float2(hm1);
    float2 m2 = __half22float2(hm2);
    float2 m3 = __half22float2(hm3);

    float sx = a0.x + a2.x, sy = a0.y + a2.y;
    float dx = a0.x - a2.x, dy = a0.y - a2.y;
    float px = m1.x - m2.x, py = m1.y - m2.y;
    float qx = m3.x - m1.x - m2.x, qy = m3.y - m1.y - m2.y;

    const float2 bv0 = *reinterpret_cast<const float2*>(bias + o2);
    const float2 bv1 = *reinterpret_cast<const float2*>(bias + 768 + o2);
    const float2 bv2 = *reinterpret_cast<const float2*>(bias + 1536 + o2);
    const float2 bv3 = *reinterpret_cast<const float2*>(bias + 2304 + o2);

    float* ob = out + (size_t)b * 3072 + o2;
    *reinterpret_cast<float2*>(ob)        = make_float2(sx + px + bv0.x, sy + py + bv0.y);
    *reinterpret_cast<float2*>(ob + 768)  = make_float2(dx + qx + bv1.x, dy + qy + bv1.y);
    *reinterpret_cast<float2*>(ob + 1536) = make_float2(sx - px + bv2.x, sy - py + bv2.y);
    *reinterpret_cast<float2*>(ob + 2304) = make_float2(dx - qx + bv3.x, dy - qy + bv3.y);
}

// ---------------------------------------------------------------------------
extern "C" void kernel_launch(void* const* d_in, const int* in_sizes, int n_in,
                              void* d_out, int out_size) {
    const float* x    = (const float*)d_in[0];
    const float* w    = (const float*)d_in[1];
    const float* bias = (const float*)d_in[2];
    float* out = (float*)d_out;

    cudaFuncSetAttribute(gemm_f16_kernel,
                         cudaFuncAttributeMaxDynamicSharedMemorySize, SMEM_BYTES);

    prep_xt_kernel<<<(M_DIM * 48) / 256, 256>>>(x);     // 1176 blocks
    prep_bp_kernel<<<11520 / 128, 128>>>(w);            // 90 blocks

    dim3 grid(30, 49);
    gemm_f16_kernel<<<grid, 256, SMEM_BYTES>>>();

    combine_kernel<<<(M_DIM * 384) / 256, 256>>>(bias, out);  // 9408 blocks
}